// round 16
// baseline (speedup 1.0000x reference)
#include <cuda_runtime.h>
#include <cuda_bf16.h>
#include <math.h>
#include <stdint.h>

// Problem constants
#define V_   32000
#define D_   1024
#define H_   16
#define HKV_ 4
#define FF_  4096
#define L_   8
#define HD_  64
#define NREP_ 4
#define B_   2
#define S_   1024
#define M_   (B_*S_)      // 2048 tokens
#define KVW_ (HKV_*HD_)   // 256
#define QW_  (H_*HD_)     // 1024
#define QKVW_ (QW_ + 2*KVW_)   // 1536
#define GUW_  (2*FF_)          // 8192

// ---------------- scratch (device globals; no allocation allowed) ----------
__device__ float g_x   [M_*D_];
__device__ float g_qkv [M_*QKVW_];
__device__ float g_gu  [M_*GUW_];
__device__ float2 g_rope[S_*32];           // (cos, sin) per (s, i)
// split (hi/lo bf16) activations
__device__ __align__(16) uint16_t g_h_hi  [M_*D_],  g_h_lo  [M_*D_];
__device__ __align__(16) uint16_t g_att_hi[M_*QW_], g_att_lo[M_*QW_];
__device__ __align__(16) uint16_t g_gs_hi [M_*FF_], g_gs_lo [M_*FF_];
// split transposed weights for ALL layers ([N,K] row-major per layer)
__device__ __align__(16) uint16_t g_wqkvt_hi[L_*QKVW_*D_], g_wqkvt_lo[L_*QKVW_*D_];
__device__ __align__(16) uint16_t g_wot_hi  [L_*D_*QW_],   g_wot_lo  [L_*D_*QW_];
__device__ __align__(16) uint16_t g_wgut_hi [L_*GUW_*D_],  g_wgut_lo [L_*GUW_*D_];
__device__ __align__(16) uint16_t g_wdt_hi  [L_*D_*FF_],   g_wdt_lo  [L_*D_*FF_];
// split embed table (for logits GEMM B operand)
__device__ __align__(16) uint16_t g_emb_hi[V_*D_], g_emb_lo[V_*D_];

// ---------------- helpers ---------------------------------------------------
__device__ __forceinline__ uint32_t smem_u32(const void* p) {
    uint32_t a;
    asm("{ .reg .u64 t; cvta.to.shared.u64 t, %1; cvt.u32.u64 %0, t; }"
        : "=r"(a) : "l"(p));
    return a;
}
__device__ __forceinline__ uint16_t bfbits(__nv_bfloat16 h) {
    return *reinterpret_cast<uint16_t*>(&h);
}
__device__ __forceinline__ void split_w(uint16_t* hi, uint16_t* lo, size_t idx, float v) {
    __nv_bfloat16 hb = __float2bfloat16_rn(v);
    float l = v - __bfloat162float(hb);
    __nv_bfloat16 lb = __float2bfloat16_rn(l);
    hi[idx] = bfbits(hb);
    lo[idx] = bfbits(lb);
}

#define CP_A16(s, g) asm volatile("cp.async.cg.shared.global [%0], [%1], 16;" :: "r"(s), "l"(g))
#define CP_COMMIT()  asm volatile("cp.async.commit_group;" ::: "memory")
#define CP_WAIT1()   asm volatile("cp.async.wait_group 1;" ::: "memory")
#define CP_WAIT0()   asm volatile("cp.async.wait_group 0;" ::: "memory")

__device__ __forceinline__ void ldm_x4(uint32_t a, uint32_t& r0, uint32_t& r1,
                                       uint32_t& r2, uint32_t& r3) {
    asm volatile("ldmatrix.sync.aligned.m8n8.x4.shared.b16 {%0,%1,%2,%3}, [%4];"
                 : "=r"(r0), "=r"(r1), "=r"(r2), "=r"(r3) : "r"(a));
}

__device__ __forceinline__ void mma_bf16_16x8x16(float* c, uint32_t a0, uint32_t a1,
                                                 uint32_t a2, uint32_t a3,
                                                 uint32_t b0, uint32_t b1) {
    asm volatile(
        "mma.sync.aligned.m16n8k16.row.col.f32.bf16.bf16.f32 "
        "{%0,%1,%2,%3}, {%4,%5,%6,%7}, {%8,%9}, {%0,%1,%2,%3};"
        : "+f"(c[0]), "+f"(c[1]), "+f"(c[2]), "+f"(c[3])
        : "r"(a0), "r"(a1), "r"(a2), "r"(a3), "r"(b0), "r"(b1));
}

// ================= bf16x3 split GEMM (NT), pre-split operands ==============
#define COMPB  (128 * 64)         // 8192 B per component
#define BUFB   (4 * COMPB)        // 32768 B per stage
#define NSTAGE 3
#define GEMM_SMEM_BYTES (NSTAGE * BUFB)   // 98304 B

__device__ __forceinline__ uint32_t swz(int row, int chunk) {
    return (uint32_t)(row * 64 + ((chunk ^ ((row >> 1) & 3)) << 4));
}

__device__ __forceinline__ void issue_tile(uint32_t sbuf,
    const uint16_t* Ahi, const uint16_t* Alo,
    const uint16_t* Bhi, const uint16_t* Blo,
    int brow, int bcol, int K, int k0, int tid)
{
#pragma unroll
    for (int c = 0; c < 2; c++) {
        int idx = tid + c * 256;
        int row = idx >> 2;
        int ch  = idx & 3;
        uint32_t so = swz(row, ch);
        size_t goA = (size_t)(brow + row) * K + k0 + ch * 8;
        size_t goB = (size_t)(bcol + row) * K + k0 + ch * 8;
        CP_A16(sbuf + so,             Ahi + goA);
        CP_A16(sbuf + COMPB + so,     Alo + goA);
        CP_A16(sbuf + 2 * COMPB + so, Bhi + goB);
        CP_A16(sbuf + 3 * COMPB + so, Blo + goB);
    }
    CP_COMMIT();
}

template <bool ACC>
__global__ __launch_bounds__(256, 2)
void bf16x3_gemm(const uint16_t* __restrict__ Ahi, const uint16_t* __restrict__ Alo,
                 const uint16_t* __restrict__ Bhi, const uint16_t* __restrict__ Blo,
                 float* __restrict__ C, int M, int N, int K) {
    extern __shared__ char smem[];
    const uint32_t sb = smem_u32(smem);
    const int tid    = threadIdx.x;
    const int wid    = tid >> 5;
    const int lane   = tid & 31;
    const int warp_m = (wid & 1) * 64;
    const int warp_n = (wid >> 1) * 32;
    const int brow   = blockIdx.y * 128;
    const int bcol   = blockIdx.x * 128;

    float acc[4][4][4];
#pragma unroll
    for (int i = 0; i < 4; i++)
#pragma unroll
        for (int j = 0; j < 4; j++)
#pragma unroll
            for (int r = 0; r < 4; r++) acc[i][j][r] = 0.f;

    const int niter = K >> 5;

    issue_tile(sb,        Ahi, Alo, Bhi, Blo, brow, bcol, K, 0,  tid);
    issue_tile(sb + BUFB, Ahi, Alo, Bhi, Blo, brow, bcol, K, 32, tid);

    const int a_r = lane & 15;
    const int a_h = (lane >> 4) & 1;
    const int b_r = ((lane >> 4) & 1) * 8 + (lane & 7);
    const int b_h = (lane >> 3) & 1;

    int s_cur = 0;
    int s_nxt = 2;
    for (int it = 0; it < niter; it++) {
        if (it + 1 < niter) CP_WAIT1(); else CP_WAIT0();
        __syncthreads();
        if (it + 2 < niter)
            issue_tile(sb + (uint32_t)s_nxt * BUFB, Ahi, Alo, Bhi, Blo,
                       brow, bcol, K, (it + 2) << 5, tid);

        const uint32_t buf = sb + (uint32_t)s_cur * BUFB;
        const uint32_t Ah = buf, Al = buf + COMPB, Bh = buf + 2 * COMPB, Bl = buf + 3 * COMPB;
#pragma unroll
        for (int ks = 0; ks < 2; ks++) {
            uint32_t bhf[2][4], blf[2][4];
#pragma unroll
            for (int pr = 0; pr < 2; pr++) {
                int brow_l = warp_n + pr * 16 + b_r;
                uint32_t off = swz(brow_l, ks * 2 + b_h);
                ldm_x4(Bh + off, bhf[pr][0], bhf[pr][1], bhf[pr][2], bhf[pr][3]);
                ldm_x4(Bl + off, blf[pr][0], blf[pr][1], blf[pr][2], blf[pr][3]);
            }
            // software-pipelined A fragments (double buffered)
            uint32_t afh[2][4], afl[2][4];
            {
                uint32_t off0 = swz(warp_m + a_r, ks * 2 + a_h);
                ldm_x4(Ah + off0, afh[0][0], afh[0][1], afh[0][2], afh[0][3]);
                ldm_x4(Al + off0, afl[0][0], afl[0][1], afl[0][2], afl[0][3]);
            }
            int cur = 0;
#pragma unroll
            for (int mt = 0; mt < 4; mt++) {
                if (mt < 3) {
                    uint32_t offn = swz(warp_m + (mt + 1) * 16 + a_r, ks * 2 + a_h);
                    ldm_x4(Ah + offn, afh[cur ^ 1][0], afh[cur ^ 1][1],
                           afh[cur ^ 1][2], afh[cur ^ 1][3]);
                    ldm_x4(Al + offn, afl[cur ^ 1][0], afl[cur ^ 1][1],
                           afl[cur ^ 1][2], afl[cur ^ 1][3]);
                }
#pragma unroll
                for (int nt = 0; nt < 4; nt++) {
                    const int pr = nt >> 1, hf = (nt & 1) * 2;
                    mma_bf16_16x8x16(acc[mt][nt], afh[cur][0], afh[cur][1],
                                     afh[cur][2], afh[cur][3],
                                     bhf[pr][hf], bhf[pr][hf + 1]);
                }
#pragma unroll
                for (int nt = 0; nt < 4; nt++) {
                    const int pr = nt >> 1, hf = (nt & 1) * 2;
                    mma_bf16_16x8x16(acc[mt][nt], afh[cur][0], afh[cur][1],
                                     afh[cur][2], afh[cur][3],
                                     blf[pr][hf], blf[pr][hf + 1]);
                }
#pragma unroll
                for (int nt = 0; nt < 4; nt++) {
                    const int pr = nt >> 1, hf = (nt & 1) * 2;
                    mma_bf16_16x8x16(acc[mt][nt], afl[cur][0], afl[cur][1],
                                     afl[cur][2], afl[cur][3],
                                     bhf[pr][hf], bhf[pr][hf + 1]);
                }
                cur ^= 1;
            }
        }
        s_cur = (s_cur == NSTAGE - 1) ? 0 : s_cur + 1;
        s_nxt = (s_nxt == NSTAGE - 1) ? 0 : s_nxt + 1;
    }

    const int g = lane >> 2, t = lane & 3;
#pragma unroll
    for (int mt = 0; mt < 4; mt++) {
        int r0 = brow + warp_m + mt * 16 + g;
#pragma unroll
        for (int nt = 0; nt < 4; nt++) {
            int c0 = bcol + warp_n + nt * 8 + t * 2;
            float2* p0 = (float2*)(C + (size_t)r0 * N + c0);
            float2* p1 = (float2*)(C + (size_t)(r0 + 8) * N + c0);
            float2 v0 = make_float2(acc[mt][nt][0], acc[mt][nt][1]);
            float2 v1 = make_float2(acc[mt][nt][2], acc[mt][nt][3]);
            if (ACC) {
                float2 o0 = *p0, o1 = *p1;
                v0.x += o0.x; v0.y += o0.y;
                v1.x += o1.x; v1.y += o1.y;
            }
            *p0 = v0;
            *p1 = v1;
        }
    }
}

// ----- batched weight transpose+split: [K,N] fp32 -> [N,K] bf16 hi/lo -------
__global__ void transpose_split_batched(const float* __restrict__ in,
                                        uint16_t* __restrict__ hi,
                                        uint16_t* __restrict__ lo,
                                        int K, int N,
                                        size_t in_lstride, size_t out_lstride) {
    __shared__ float tile[32][33];
    int z = blockIdx.z;
    in += (size_t)z * in_lstride;
    hi += (size_t)z * out_lstride;
    lo += (size_t)z * out_lstride;
    int kx = blockIdx.x * 32, ny = blockIdx.y * 32;
    int tx = threadIdx.x, ty = threadIdx.y;
#pragma unroll
    for (int r = ty; r < 32; r += 8)
        tile[r][tx] = in[(size_t)(kx + r) * N + ny + tx];
    __syncthreads();
#pragma unroll
    for (int r = ty; r < 32; r += 8)
        split_w(hi, lo, (size_t)(ny + r) * K + kx + tx, tile[tx][r]);
}

// ------------- elementwise split (embed table) ------------------------------
__global__ void split4_kernel(const float4* __restrict__ in,
                              uint2* __restrict__ hi, uint2* __restrict__ lo, int n4) {
    int i = blockIdx.x * blockDim.x + threadIdx.x;
    if (i >= n4) return;
    float4 v = in[i];
    __nv_bfloat16 h0 = __float2bfloat16_rn(v.x), h1 = __float2bfloat16_rn(v.y);
    __nv_bfloat16 h2 = __float2bfloat16_rn(v.z), h3 = __float2bfloat16_rn(v.w);
    __nv_bfloat16 l0 = __float2bfloat16_rn(v.x - __bfloat162float(h0));
    __nv_bfloat16 l1 = __float2bfloat16_rn(v.y - __bfloat162float(h1));
    __nv_bfloat16 l2 = __float2bfloat16_rn(v.z - __bfloat162float(h2));
    __nv_bfloat16 l3 = __float2bfloat16_rn(v.w - __bfloat162float(h3));
    hi[i] = make_uint2((uint32_t)bfbits(h0) | ((uint32_t)bfbits(h1) << 16),
                       (uint32_t)bfbits(h2) | ((uint32_t)bfbits(h3) << 16));
    lo[i] = make_uint2((uint32_t)bfbits(l0) | ((uint32_t)bfbits(l1) << 16),
                       (uint32_t)bfbits(l2) | ((uint32_t)bfbits(l3) << 16));
}

// ---------------- rope cos/sin table ----------------------------------------
__global__ void rope_table_kernel(float2* __restrict__ tab) {
    int idx = blockIdx.x * blockDim.x + threadIdx.x;
    if (idx >= S_ * 32) return;
    int s = idx >> 5, i = idx & 31;
    float inv_freq = expf(-(float)(2 * i) * (1.0f / 64.0f) * 9.210340371976184f);
    float ang = (float)s * inv_freq;
    float sn, cs;
    sincosf(ang, &sn, &cs);
    tab[idx] = make_float2(cs, sn);
}

// ---------------- embedding gather ----------------------------------------
__global__ void embed_kernel(const int* __restrict__ tokens,
                             const float* __restrict__ embed,
                             float* __restrict__ x) {
    int m = blockIdx.x;
    int tkn = tokens[m];
    const float4* src = (const float4*)(embed + (size_t)tkn * D_);
    float4*       dst = (float4*)(x + (size_t)m * D_);
    for (int i = threadIdx.x; i < D_ / 4; i += blockDim.x) dst[i] = src[i];
}

// ---------------- RMSNorm -> split bf16 output ------------------------------
__global__ void rmsnorm_split_kernel(const float* __restrict__ x,
                                     const float* __restrict__ w,
                                     uint16_t* __restrict__ hi,
                                     uint16_t* __restrict__ lo) {
    int m = blockIdx.x;
    const float4* xr4 = (const float4*)(x + (size_t)m * D_);
    float ss = 0.f;
    float4 v = xr4[threadIdx.x];          // 256 threads x 4 = 1024
    ss = v.x * v.x + v.y * v.y + v.z * v.z + v.w * v.w;
    ss += __shfl_xor_sync(0xffffffffu, ss, 16);
    ss += __shfl_xor_sync(0xffffffffu, ss, 8);
    ss += __shfl_xor_sync(0xffffffffu, ss, 4);
    ss += __shfl_xor_sync(0xffffffffu, ss, 2);
    ss += __shfl_xor_sync(0xffffffffu, ss, 1);
    __shared__ float red[8];
    int wid = threadIdx.x >> 5, lane = threadIdx.x & 31;
    if (lane == 0) red[wid] = ss;
    __syncthreads();
    float tot = red[0] + red[1] + red[2] + red[3] + red[4] + red[5] + red[6] + red[7];
    float rn = rsqrtf(tot / (float)D_ + 1e-6f);
    const float4* w4 = (const float4*)w;
    float4 wv = w4[threadIdx.x];
    size_t base = (size_t)m * D_ + threadIdx.x * 4;
    split_w(hi, lo, base,     v.x * rn * wv.x);
    split_w(hi, lo, base + 1, v.y * rn * wv.y);
    split_w(hi, lo, base + 2, v.z * rn * wv.z);
    split_w(hi, lo, base + 3, v.w * rn * wv.w);
}

// -------- tile-parallel causal attention with fused RoPE --------------------
#define AT_TK 32
__global__ __launch_bounds__(256)
void attn_kernel(const float* __restrict__ qkv,
                 const float2* __restrict__ rope_tab,
                 uint16_t* __restrict__ out_hi,
                 uint16_t* __restrict__ out_lo) {
    __shared__ float Ks[AT_TK][68];
    __shared__ float Vs[AT_TK][68];
    __shared__ float Qs[8][64];
    __shared__ float Ps[8][AT_TK];

    const int bg   = blockIdx.x;
    const int b    = bg / HKV_;
    const int g    = bg % HKV_;
    const int wid  = threadIdx.x >> 5;
    const int lane = threadIdx.x & 31;
    const int head = g * NREP_ + (wid >> 1);
    const int s    = blockIdx.y * 2 + (wid & 1);
    const int smax = blockIdx.y * 2 + 1;

    // load q + apply RoPE (pairs d <-> d+32 via shfl_xor 16)
    {
        const float2* qp = (const float2*)(qkv + (size_t)(b * S_ + s) * QKVW_ + head * HD_);
        float2 qv = qp[lane];
        float px = __shfl_xor_sync(0xffffffffu, qv.x, 16);
        float py = __shfl_xor_sync(0xffffffffu, qv.y, 16);
        int i2 = (lane & 15) * 2;
        float4 cs4 = *(const float4*)&rope_tab[s * 32 + i2];  // c0,s0,c1,s1
        float rx, ry;
        if (lane < 16) { rx = qv.x * cs4.x - px * cs4.y; ry = qv.y * cs4.z - py * cs4.w; }
        else           { rx = px * cs4.y + qv.x * cs4.x; ry = py * cs4.w + qv.y * cs4.z; }
        Qs[wid][2 * lane]     = rx;
        Qs[wid][2 * lane + 1] = ry;
    }

    const float* kbase = qkv + (size_t)b * S_ * QKVW_ + QW_ + g * HD_;
    const float* vbase = kbase + KVW_;

    float m = -INFINITY, l = 0.f;
    float o0a = 0.f, o1a = 0.f, o0b = 0.f, o1b = 0.f;
    const int ntiles = (smax + AT_TK) / AT_TK;

    for (int t = 0; t < ntiles; t++) {
        const int j0 = t * AT_TK;
        __syncthreads();
#pragma unroll
        for (int c = 0; c < 2; c++) {
            int u   = threadIdx.x + c * 256;
            int key = u >> 4, d4 = u & 15;
            int j   = j0 + key;
            float4 kk = make_float4(0.f, 0.f, 0.f, 0.f), vv = kk;
            if (j < S_) {
                kk = *(const float4*)(kbase + (size_t)j * QKVW_ + d4 * 4);
                vv = *(const float4*)(vbase + (size_t)j * QKVW_ + d4 * 4);
            }
            *(float4*)&Ks[key][d4 * 4] = kk;
            *(float4*)&Vs[key][d4 * 4] = vv;
        }
        __syncthreads();
        // apply RoPE to K tile in smem: 32 keys x 32 pairs
#pragma unroll
        for (int c = 0; c < 4; c++) {
            int u = threadIdx.x + c * 256;
            int key = u >> 5, i = u & 31;
            int j = j0 + key;
            if (j < S_) {
                float2 cs2 = rope_tab[j * 32 + i];
                float x1 = Ks[key][i];
                float x2 = Ks[key][i + 32];
                Ks[key][i]      = x1 * cs2.x - x2 * cs2.y;
                Ks[key][i + 32] = x2 * cs2.x + x1 * cs2.y;
            }
        }
        __syncthreads();

        const int j = j0 + lane;
        float sc = -INFINITY;
        if (j <= s) {
            float acc0 = 0.f, acc1 = 0.f;
#pragma unroll
            for (int d4 = 0; d4 < 16; d4 += 2) {
                float4 k0 = *(const float4*)&Ks[lane][d4 * 4];
                float4 q0 = *(const float4*)&Qs[wid][d4 * 4];
                acc0 += k0.x * q0.x + k0.y * q0.y + k0.z * q0.z + k0.w * q0.w;
                float4 k1 = *(const float4*)&Ks[lane][d4 * 4 + 4];
                float4 q1 = *(const float4*)&Qs[wid][d4 * 4 + 4];
                acc1 += k1.x * q1.x + k1.y * q1.y + k1.z * q1.z + k1.w * q1.w;
            }
            sc = (acc0 + acc1) * 0.125f;
        }
        float tm = sc;
        tm = fmaxf(tm, __shfl_xor_sync(0xffffffffu, tm, 16));
        tm = fmaxf(tm, __shfl_xor_sync(0xffffffffu, tm, 8));
        tm = fmaxf(tm, __shfl_xor_sync(0xffffffffu, tm, 4));
        tm = fmaxf(tm, __shfl_xor_sync(0xffffffffu, tm, 2));
        tm = fmaxf(tm, __shfl_xor_sync(0xffffffffu, tm, 1));
        float mn   = fmaxf(m, tm);
        float corr = __expf(m - mn);
        float p    = (j <= s) ? __expf(sc - mn) : 0.f;
        float ps = p;
        ps += __shfl_xor_sync(0xffffffffu, ps, 16);
        ps += __shfl_xor_sync(0xffffffffu, ps, 8);
        ps += __shfl_xor_sync(0xffffffffu, ps, 4);
        ps += __shfl_xor_sync(0xffffffffu, ps, 2);
        ps += __shfl_xor_sync(0xffffffffu, ps, 1);
        l = l * corr + ps;
        o0a *= corr; o1a *= corr; o0b *= corr; o1b *= corr;
        m = mn;

        Ps[wid][lane] = p;
        __syncwarp();
#pragma unroll
        for (int jj = 0; jj < AT_TK; jj += 2) {
            float p0 = Ps[wid][jj];
            float p1 = Ps[wid][jj + 1];
            o0a += p0 * Vs[jj][2 * lane];
            o1a += p0 * Vs[jj][2 * lane + 1];
            o0b += p1 * Vs[jj + 1][2 * lane];
            o1b += p1 * Vs[jj + 1][2 * lane + 1];
        }
        __syncwarp();
    }

    float invl = 1.f / l;
    size_t base_idx = (size_t)(b * S_ + s) * QW_ + head * HD_ + lane * 2;
    split_w(out_hi, out_lo, base_idx,     (o0a + o0b) * invl);
    split_w(out_hi, out_lo, base_idx + 1, (o1a + o1b) * invl);
}

// ------- SiLU(gate)*up from fused gu buffer -> split bf16 -------------------
__global__ void silumul_split_kernel(const float* __restrict__ gu,
                                     uint16_t* __restrict__ hi,
                                     uint16_t* __restrict__ lo, int n) {
    int idx = blockIdx.x * blockDim.x + threadIdx.x;
    if (idx >= n) return;
    int m = idx >> 12;          // / FF_
    int j = idx & (FF_ - 1);
    float gv = gu[(size_t)m * GUW_ + j];
    float uv = gu[(size_t)m * GUW_ + FF_ + j];
    float sig = 1.f / (1.f + __expf(-gv));
    split_w(hi, lo, idx, gv * sig * uv);
}

// ---------------- driver ----------------------------------------------------
extern "C" void kernel_launch(void* const* d_in, const int* in_sizes, int n_in,
                              void* d_out, int out_size) {
    const int*   tokens     = (const int*)d_in[0];
    const float* embed      = (const float*)d_in[1];
    const float* wq         = (const float*)d_in[2];
    const float* wk         = (const float*)d_in[3];
    const float* wv         = (const float*)d_in[4];
    const float* wo         = (const float*)d_in[5];
    const float* w_gate     = (const float*)d_in[6];
    const float* w_up       = (const float*)d_in[7];
    const float* w_down     = (const float*)d_in[8];
    const float* norm1_w    = (const float*)d_in[9];
    const float* norm2_w    = (const float*)d_in[10];
    const float* final_norm = (const float*)d_in[11];
    float* out = (float*)d_out;

    float *x, *qkv, *gu;
    float2* rope_tab;
    uint16_t *h_hi, *h_lo, *att_hi, *att_lo, *gs_hi, *gs_lo;
    uint16_t *wqkvt_hi, *wqkvt_lo, *wot_hi, *wot_lo, *wgut_hi, *wgut_lo, *wdt_hi, *wdt_lo;
    uint16_t *emb_hi, *emb_lo;
    cudaGetSymbolAddress((void**)&x,    g_x);
    cudaGetSymbolAddress((void**)&qkv,  g_qkv);
    cudaGetSymbolAddress((void**)&gu,   g_gu);
    cudaGetSymbolAddress((void**)&rope_tab, g_rope);
    cudaGetSymbolAddress((void**)&h_hi,   g_h_hi);
    cudaGetSymbolAddress((void**)&h_lo,   g_h_lo);
    cudaGetSymbolAddress((void**)&att_hi, g_att_hi);
    cudaGetSymbolAddress((void**)&att_lo, g_att_lo);
    cudaGetSymbolAddress((void**)&gs_hi,  g_gs_hi);
    cudaGetSymbolAddress((void**)&gs_lo,  g_gs_lo);
    cudaGetSymbolAddress((void**)&wqkvt_hi, g_wqkvt_hi);
    cudaGetSymbolAddress((void**)&wqkvt_lo, g_wqkvt_lo);
    cudaGetSymbolAddress((void**)&wot_hi,   g_wot_hi);
    cudaGetSymbolAddress((void**)&wot_lo,   g_wot_lo);
    cudaGetSymbolAddress((void**)&wgut_hi,  g_wgut_hi);
    cudaGetSymbolAddress((void**)&wgut_lo,  g_wgut_lo);
    cudaGetSymbolAddress((void**)&wdt_hi,   g_wdt_hi);
    cudaGetSymbolAddress((void**)&wdt_lo,   g_wdt_lo);
    cudaGetSymbolAddress((void**)&emb_hi,   g_emb_hi);
    cudaGetSymbolAddress((void**)&emb_lo,   g_emb_lo);

    cudaFuncSetAttribute(bf16x3_gemm<false>,
                         cudaFuncAttributeMaxDynamicSharedMemorySize, GEMM_SMEM_BYTES);
    cudaFuncSetAttribute(bf16x3_gemm<true>,
                         cudaFuncAttributeMaxDynamicSharedMemorySize, GEMM_SMEM_BYTES);

    embed_kernel<<<M_, 256>>>(tokens, embed, x);
    rope_table_kernel<<<(S_ * 32 + 255) / 256, 256>>>(rope_tab);
    split4_kernel<<<(V_ * D_ / 4 + 255) / 256, 256>>>((const float4*)embed,
                                                      (uint2*)emb_hi, (uint2*)emb_lo,
                                                      V_ * D_ / 4);

    dim3 t32(32, 8);
    const size_t QKV_L = (size_t)QKVW_ * D_;
    const size_t GU_L  = (size_t)GUW_ * D_;
    transpose_split_batched<<<dim3(D_ / 32, QW_ / 32, L_), t32>>>(
        wq, wqkvt_hi, wqkvt_lo, D_, QW_, (size_t)D_ * QW_, QKV_L);
    transpose_split_batched<<<dim3(D_ / 32, KVW_ / 32, L_), t32>>>(
        wk, wqkvt_hi + (size_t)QW_ * D_, wqkvt_lo + (size_t)QW_ * D_,
        D_, KVW_, (size_t)D_ * KVW_, QKV_L);
    transpose_split_batched<<<dim3(D_ / 32, KVW_ / 32, L_), t32>>>(
        wv, wqkvt_hi + (size_t)(QW_ + KVW_) * D_, wqkvt_lo + (size_t)(QW_ + KVW_) * D_,
        D_, KVW_, (size_t)D_ * KVW_, QKV_L);
    transpose_split_batched<<<dim3(QW_ / 32, D_ / 32, L_), t32>>>(
        wo, wot_hi, wot_lo, QW_, D_, (size_t)QW_ * D_, (size_t)D_ * QW_);
    transpose_split_batched<<<dim3(D_ / 32, FF_ / 32, L_), t32>>>(
        w_gate, wgut_hi, wgut_lo, D_, FF_, (size_t)D_ * FF_, GU_L);
    transpose_split_batched<<<dim3(D_ / 32, FF_ / 32, L_), t32>>>(
        w_up, wgut_hi + (size_t)FF_ * D_, wgut_lo + (size_t)FF_ * D_,
        D_, FF_, (size_t)D_ * FF_, GU_L);
    transpose_split_batched<<<dim3(FF_ / 32, D_ / 32, L_), t32>>>(
        w_down, wdt_hi, wdt_lo, FF_, D_, (size_t)FF_ * D_, (size_t)D_ * FF_);

    for (int i = 0; i < L_; i++) {
        const uint16_t* wqkvt_hi_i = wqkvt_hi + (size_t)i * QKV_L;
        const uint16_t* wqkvt_lo_i = wqkvt_lo + (size_t)i * QKV_L;
        const uint16_t* wot_hi_i   = wot_hi + (size_t)i * D_ * QW_;
        const uint16_t* wot_lo_i   = wot_lo + (size_t)i * D_ * QW_;
        const uint16_t* wgut_hi_i  = wgut_hi + (size_t)i * GU_L;
        const uint16_t* wgut_lo_i  = wgut_lo + (size_t)i * GU_L;
        const uint16_t* wdt_hi_i   = wdt_hi + (size_t)i * D_ * FF_;
        const uint16_t* wdt_lo_i   = wdt_lo + (size_t)i * D_ * FF_;

        rmsnorm_split_kernel<<<M_, 256>>>(x, norm1_w + (size_t)i * D_, h_hi, h_lo);

        bf16x3_gemm<false><<<dim3(QKVW_ / 128, M_ / 128), 256, GEMM_SMEM_BYTES>>>(
            h_hi, h_lo, wqkvt_hi_i, wqkvt_lo_i, qkv, M_, QKVW_, D_);

        attn_kernel<<<dim3(B_ * HKV_, S_ / 2), 256>>>(qkv, rope_tab, att_hi, att_lo);

        bf16x3_gemm<true><<<dim3(D_ / 128, M_ / 128), 256, GEMM_SMEM_BYTES>>>(
            att_hi, att_lo, wot_hi_i, wot_lo_i, x, M_, D_, QW_);

        rmsnorm_split_kernel<<<M_, 256>>>(x, norm2_w + (size_t)i * D_, h_hi, h_lo);

        bf16x3_gemm<false><<<dim3(GUW_ / 128, M_ / 128), 256, GEMM_SMEM_BYTES>>>(
            h_hi, h_lo, wgut_hi_i, wgut_lo_i, gu, M_, GUW_, D_);

        silumul_split_kernel<<<(M_ * FF_ + 255) / 256, 256>>>(gu, gs_hi, gs_lo, M_ * FF_);

        bf16x3_gemm<true><<<dim3(D_ / 128, M_ / 128), 256, GEMM_SMEM_BYTES>>>(
            gs_hi, gs_lo, wdt_hi_i, wdt_lo_i, x, M_, D_, FF_);
    }

    rmsnorm_split_kernel<<<M_, 256>>>(x, final_norm, h_hi, h_lo);

    bf16x3_gemm<false><<<dim3(V_ / 128, M_ / 128), 256, GEMM_SMEM_BYTES>>>(
        h_hi, h_lo, emb_hi, emb_lo, out, M_, V_, D_);
}